// round 6
// baseline (speedup 1.0000x reference)
#include <cuda_runtime.h>
#include <cuda_bf16.h>

#define K_FEAT 4096
#define N_CTRL 256
#define M_INT  254       // interior knots
#define R_PER  4         // gamma rows per thread (kernel 1)
#define HALF   12        // conv half-width; truncation rho^13 ~ 3.6e-8
#define WIN    (R_PER + 2 * HALF)   // 28 taps per thread group
#define PMAX   64        // signed-power table (zeros beyond 48)

// gamma scratch: 4 MB static device mem (no allocations allowed).
__device__ float g_gamma[N_CTRL * K_FEAT];

// ---------------------------------------------------------------------------
// Kernel 1: gamma via closed-form inverse of the uniform [1 4 1] system.
// (M^-1)_{pj} = A*rho^|p-j| - A*rho^(p+j+2) - A*rho^(2m-p-j),
// rho = -(2-sqrt(3)), A = 1/(2*sqrt(3)).  Each thread owns 4 consecutive
// gamma rows x one float4 k-chunk: 28-tap window shared across the 4 rows
// (weights block-uniform, staged in smem; zero outside validity). All loads
// independent -> latency hidden; no serial chain, no dp scratch.
// Grid (4, 64) = 256 blocks of 256.
// ---------------------------------------------------------------------------
__global__ void __launch_bounds__(256) spline_gamma_kernel(const float* __restrict__ values) {
    __shared__ float P[PMAX];
    __shared__ float W[R_PER][WIN];

    const int tid = threadIdx.x;
    const int g0  = blockIdx.y * R_PER;       // first gamma row of group (0..252)
    const int jlo = g0 - 1 - HALF;            // first tap (interior row index)

    if (tid == 0) {
        const float rho = -0.26794919243112270647f;   // -(2-sqrt(3))
        float p = 1.0f;
        #pragma unroll
        for (int d = 0; d < 48; d++) { P[d] = p; p *= rho; }
        #pragma unroll
        for (int d = 48; d < PMAX; d++) P[d] = 0.0f;
    }
    __syncthreads();
    if (tid < R_PER * WIN) {
        const int r = tid / WIN;              // row within group
        const int u = tid % WIN;              // tap within window
        const int g = g0 + r;                 // gamma row (0..255)
        const int p = g - 1;                  // interior index
        const int j = jlo + u;
        const float ACP = 0.28867513459481288225f * 6.0f * 255.0f * 255.0f; // A*6/h^2
        float wv = 0.0f;
        if (g >= 1 && g <= M_INT && j >= 0 && j < M_INT && abs(j - p) <= HALF)
            wv = ACP * (P[abs(j - p)] - P[min(j + p + 2, PMAX - 1)]
                        - P[min(2 * M_INT - j - p, PMAX - 1)]);
        W[r][u] = wv;
    }
    __syncthreads();

    const int k = (blockIdx.x * 256 + tid) * 4;
    #define VROW(r) (*reinterpret_cast<const float4*>(values + (size_t)(r) * K_FEAT + k))

    const int first = jlo < 0 ? 0 : jlo;
    float4 v0 = VROW(first);
    float4 v1 = VROW(first + 1);
    float4 acc[R_PER];
    #pragma unroll
    for (int r = 0; r < R_PER; r++) acc[r] = make_float4(0.f, 0.f, 0.f, 0.f);

    #pragma unroll
    for (int u = 0; u < WIN; u++) {
        const int j = jlo + u;
        if (j >= 0 && j < M_INT) {
            float4 v2 = VROW(j + 2);
            float rx = (v2.x - v1.x) - (v1.x - v0.x);
            float ry = (v2.y - v1.y) - (v1.y - v0.y);
            float rz = (v2.z - v1.z) - (v1.z - v0.z);
            float rw = (v2.w - v1.w) - (v1.w - v0.w);
            #pragma unroll
            for (int r = 0; r < R_PER; r++) {
                const float wv = W[r][u];
                acc[r].x = fmaf(wv, rx, acc[r].x);
                acc[r].y = fmaf(wv, ry, acc[r].y);
                acc[r].z = fmaf(wv, rz, acc[r].z);
                acc[r].w = fmaf(wv, rw, acc[r].w);
            }
            v0 = v1; v1 = v2;
        }
    }

    #pragma unroll
    for (int r = 0; r < R_PER; r++)
        *reinterpret_cast<float4*>(g_gamma + (size_t)(g0 + r) * K_FEAT + k) = acc[r];
    #undef VROW
}

// ---------------------------------------------------------------------------
// Kernel 2: evaluation (unchanged from the 23.2us-measured version).
// One thread owns (segment s, one float4 of k); loads y0,y1,gamma0,gamma1
// into registers once, streams the ~32 eval rows with evict-first stores.
// ---------------------------------------------------------------------------
__global__ void __launch_bounds__(256) spline_eval_kernel(
    const float* __restrict__ values, float* __restrict__ out, int ne1) {

    const int s = blockIdx.y;                                // 0..254
    const int k = (blockIdx.x * blockDim.x + threadIdx.x) * 4;

    const float4 y0 = *reinterpret_cast<const float4*>(values  + (size_t)s       * K_FEAT + k);
    const float4 y1 = *reinterpret_cast<const float4*>(values  + (size_t)(s + 1) * K_FEAT + k);
    const float4 q0 = *reinterpret_cast<const float4*>(g_gamma + (size_t)s       * K_FEAT + k);
    const float4 q1 = *reinterpret_cast<const float4*>(g_gamma + (size_t)(s + 1) * K_FEAT + k);

    const int jstart = (s * ne1 + 254) / 255;                // ceil(s*ne1/255)
    const int jend   = (s < 254) ? ((s + 1) * ne1 + 254) / 255 - 1 : ne1;

    const float inv_ne1 = 1.0f / (float)ne1;
    const float w = 1.0f / (6.0f * 255.0f * 255.0f);         // h^2/6
    const int base = s * ne1;

    #pragma unroll 4
    for (int j = jstart; j <= jend; j++) {
        float b  = (float)(j * 255 - base) * inv_ne1;        // in [0,1]
        float a  = 1.0f - b;
        float wa = (a * a * a - a) * w;
        float wb = (b * b * b - b) * w;
        float4 o;
        o.x = fmaf(a, y0.x, fmaf(b, y1.x, fmaf(wa, q0.x, wb * q1.x)));
        o.y = fmaf(a, y0.y, fmaf(b, y1.y, fmaf(wa, q0.y, wb * q1.y)));
        o.z = fmaf(a, y0.z, fmaf(b, y1.z, fmaf(wa, q0.z, wb * q1.z)));
        o.w = fmaf(a, y0.w, fmaf(b, y1.w, fmaf(wa, q0.w, wb * q1.w)));
        __stcs(reinterpret_cast<float4*>(out + (size_t)j * K_FEAT + k), o);
    }
}

extern "C" void kernel_launch(void* const* d_in, const int* in_sizes, int n_in,
                              void* d_out, int out_size) {
    const float* values = (const float*)d_in[0];
    float* out = (float*)d_out;

    const int n_eval = out_size / K_FEAT;
    const int ne1 = n_eval - 1;

    dim3 ggrid(K_FEAT / (256 * 4), N_CTRL / R_PER);          // (4, 64)
    spline_gamma_kernel<<<ggrid, 256>>>(values);

    dim3 egrid(K_FEAT / (256 * 4), N_CTRL - 1);              // (4, 255)
    spline_eval_kernel<<<egrid, 256>>>(values, out, ne1);
}

// round 9
// speedup vs baseline: 1.0046x; 1.0046x over previous
#include <cuda_runtime.h>
#include <cuda_bf16.h>

#define K_FEAT 4096
#define N_CTRL 256
#define M_INT  254       // interior knots
#define R_PER  4         // gamma rows per thread (kernel 1)
#define HALF   10        // conv half-width; truncation rho^11 ~ 5e-7
#define WIN    (R_PER + 2 * HALF)   // 24 taps per thread group
#define PMAX   64        // signed-power table (zeros beyond 48)

// gamma scratch: 4 MB static device mem (no allocations allowed).
__device__ float g_gamma[N_CTRL * K_FEAT];

__device__ __forceinline__ float4 load_row_clamped(const float* __restrict__ values,
                                                   int row, int k) {
    int r = row < 0 ? 0 : (row > N_CTRL - 1 ? N_CTRL - 1 : row);
    return *reinterpret_cast<const float4*>(values + (size_t)r * K_FEAT + k);
}

// ---------------------------------------------------------------------------
// Kernel 1: gamma via closed-form inverse of the uniform [1 4 1] system.
// (M^-1)_{pj} = A*rho^|p-j| - A*rho^(p+j+2) - A*rho^(2m-p-j),
// rho = -(2-sqrt(3)), A = 1/(2*sqrt(3)).
// ALL loads are unconditional: per-slot row index clamp(jlo+u, 0, 255) keeps
// the rolling 3-row second-difference window exact at every valid tap, and
// the weight table is exactly 0 for invalid taps, so clamped rows contribute
// nothing. ptxas can front-batch 26 independent LDG.128 -> latency hidden.
// ---------------------------------------------------------------------------
__global__ void __launch_bounds__(256) spline_gamma_kernel(const float* __restrict__ values) {
    __shared__ float P[PMAX];
    __shared__ float W[R_PER][WIN];

    const int tid = threadIdx.x;
    const int g0  = blockIdx.y * R_PER;       // first gamma row of group (0..252)
    const int jlo = g0 - 1 - HALF;            // tap index of slot u=0

    if (tid == 0) {
        const float rho = -0.26794919243112270647f;   // -(2-sqrt(3))
        const float ACP = 0.28867513459481288225f * 6.0f * 255.0f * 255.0f; // A*6/h^2
        float pw = 1.0f;
        for (int d = 0; d < 48; d++) { P[d] = pw; pw *= rho; }
        for (int d = 48; d < PMAX; d++) P[d] = 0.0f;
        for (int r = 0; r < R_PER; r++) {
            const int g = g0 + r;             // gamma row (0..255)
            const int p = g - 1;              // interior index
            for (int u = 0; u < WIN; u++) {
                const int j = jlo + u;
                float wv = 0.0f;
                if (g >= 1 && g <= M_INT && j >= 0 && j < M_INT && abs(j - p) <= HALF) {
                    int d0 = abs(j - p);
                    int d1 = j + p + 2;          if (d1 > PMAX - 1) d1 = PMAX - 1;
                    int d2 = 2 * M_INT - j - p;  if (d2 > PMAX - 1) d2 = PMAX - 1;
                    wv = ACP * (P[d0] - P[d1] - P[d2]);
                }
                W[r][u] = wv;
            }
        }
    }
    __syncthreads();

    const int k = (blockIdx.x * 256 + tid) * 4;

    float4 v0 = load_row_clamped(values, jlo, k);
    float4 v1 = load_row_clamped(values, jlo + 1, k);
    float4 acc[R_PER];
    #pragma unroll
    for (int r = 0; r < R_PER; r++) acc[r] = make_float4(0.f, 0.f, 0.f, 0.f);

    #pragma unroll
    for (int u = 0; u < WIN; u++) {
        float4 v2 = load_row_clamped(values, jlo + u + 2, k);   // unconditional
        float rx = (v2.x - v1.x) - (v1.x - v0.x);
        float ry = (v2.y - v1.y) - (v1.y - v0.y);
        float rz = (v2.z - v1.z) - (v1.z - v0.z);
        float rw = (v2.w - v1.w) - (v1.w - v0.w);
        #pragma unroll
        for (int r = 0; r < R_PER; r++) {
            const float wv = W[r][u];
            acc[r].x = fmaf(wv, rx, acc[r].x);
            acc[r].y = fmaf(wv, ry, acc[r].y);
            acc[r].z = fmaf(wv, rz, acc[r].z);
            acc[r].w = fmaf(wv, rw, acc[r].w);
        }
        v0 = v1; v1 = v2;
    }

    #pragma unroll
    for (int r = 0; r < R_PER; r++)
        *reinterpret_cast<float4*>(g_gamma + (size_t)(g0 + r) * K_FEAT + k) = acc[r];
}

// ---------------------------------------------------------------------------
// Kernel 2: evaluation (unchanged; measured 23.2us across three rounds).
// One thread owns (segment s, one float4 of k); loads y0,y1,gamma0,gamma1
// into registers once, streams the ~32 eval rows with evict-first stores.
// ---------------------------------------------------------------------------
__global__ void __launch_bounds__(256) spline_eval_kernel(
    const float* __restrict__ values, float* __restrict__ out, int ne1) {

    const int s = blockIdx.y;                                // 0..254
    const int k = (blockIdx.x * blockDim.x + threadIdx.x) * 4;

    const float4 y0 = *reinterpret_cast<const float4*>(values  + (size_t)s       * K_FEAT + k);
    const float4 y1 = *reinterpret_cast<const float4*>(values  + (size_t)(s + 1) * K_FEAT + k);
    const float4 q0 = *reinterpret_cast<const float4*>(g_gamma + (size_t)s       * K_FEAT + k);
    const float4 q1 = *reinterpret_cast<const float4*>(g_gamma + (size_t)(s + 1) * K_FEAT + k);

    const int jstart = (s * ne1 + 254) / 255;                // ceil(s*ne1/255)
    const int jend   = (s < 254) ? ((s + 1) * ne1 + 254) / 255 - 1 : ne1;

    const float inv_ne1 = 1.0f / (float)ne1;
    const float w = 1.0f / (6.0f * 255.0f * 255.0f);         // h^2/6
    const int base = s * ne1;

    #pragma unroll 4
    for (int j = jstart; j <= jend; j++) {
        float b  = (float)(j * 255 - base) * inv_ne1;        // in [0,1]
        float a  = 1.0f - b;
        float wa = (a * a * a - a) * w;
        float wb = (b * b * b - b) * w;
        float4 o;
        o.x = fmaf(a, y0.x, fmaf(b, y1.x, fmaf(wa, q0.x, wb * q1.x)));
        o.y = fmaf(a, y0.y, fmaf(b, y1.y, fmaf(wa, q0.y, wb * q1.y)));
        o.z = fmaf(a, y0.z, fmaf(b, y1.z, fmaf(wa, q0.z, wb * q1.z)));
        o.w = fmaf(a, y0.w, fmaf(b, y1.w, fmaf(wa, q0.w, wb * q1.w)));
        __stcs(reinterpret_cast<float4*>(out + (size_t)j * K_FEAT + k), o);
    }
}

extern "C" void kernel_launch(void* const* d_in, const int* in_sizes, int n_in,
                              void* d_out, int out_size) {
    const float* values = (const float*)d_in[0];
    float* out = (float*)d_out;

    const int n_eval = out_size / K_FEAT;
    const int ne1 = n_eval - 1;

    dim3 ggrid(K_FEAT / (256 * 4), N_CTRL / R_PER);          // (4, 64)
    spline_gamma_kernel<<<ggrid, 256>>>(values);

    dim3 egrid(K_FEAT / (256 * 4), N_CTRL - 1);              // (4, 255)
    spline_eval_kernel<<<egrid, 256>>>(values, out, ne1);
}

// round 12
// speedup vs baseline: 1.1338x; 1.1286x over previous
#include <cuda_runtime.h>
#include <cuda_bf16.h>

#define K_FEAT 4096
#define N_CTRL 256
#define M_INT  254       // interior knots
#define R_PER  2         // gamma rows per thread (kernel 1)
#define HALF   6         // conv half-width; truncation ~rho^7 -> ~1e-7 in rel_err
#define WIN    (R_PER + 2 * HALF)   // 14 taps per thread group
#define PMAX   64        // signed-power table (zeros beyond 48)

// gamma scratch: 4 MB static device mem (no allocations allowed).
__device__ float g_gamma[N_CTRL * K_FEAT];

__device__ __forceinline__ float4 load_row_clamped(const float* __restrict__ values,
                                                   int row, int k) {
    int r = row < 0 ? 0 : (row > N_CTRL - 1 ? N_CTRL - 1 : row);
    return *reinterpret_cast<const float4*>(values + (size_t)r * K_FEAT + k);
}

// ---------------------------------------------------------------------------
// Kernel 1: gamma via closed-form inverse of the uniform [1 4 1] system.
// (M^-1)_{pj} = A*rho^|p-j| - A*rho^(p+j+2) - A*rho^(2m-p-j),
// rho = -(2-sqrt(3)), A = 1/(2*sqrt(3)).  The kernel was FMA/issue-bound at
// R_PER=4/HALF=10 (384 FMA/thread); R_PER=2/HALF=6 cuts to 112 FMA/thread and
// doubles the block count (512). Loads unconditional via row clamp; weight
// table is exactly 0 for invalid taps so clamped rows contribute nothing.
// ---------------------------------------------------------------------------
__global__ void __launch_bounds__(256) spline_gamma_kernel(const float* __restrict__ values) {
    __shared__ float P[PMAX];
    __shared__ float W[R_PER][WIN];

    const int tid = threadIdx.x;
    const int g0  = blockIdx.y * R_PER;       // first gamma row of group (0..254)
    const int jlo = g0 - 1 - HALF;            // tap index of slot u=0

    if (tid == 0) {
        const float rho = -0.26794919243112270647f;   // -(2-sqrt(3))
        const float ACP = 0.28867513459481288225f * 6.0f * 255.0f * 255.0f; // A*6/h^2
        float pw = 1.0f;
        for (int d = 0; d < 48; d++) { P[d] = pw; pw *= rho; }
        for (int d = 48; d < PMAX; d++) P[d] = 0.0f;
        for (int r = 0; r < R_PER; r++) {
            const int g = g0 + r;             // gamma row (0..255)
            const int p = g - 1;              // interior index
            for (int u = 0; u < WIN; u++) {
                const int j = jlo + u;
                float wv = 0.0f;
                if (g >= 1 && g <= M_INT && j >= 0 && j < M_INT && abs(j - p) <= HALF) {
                    int d0 = abs(j - p);
                    int d1 = j + p + 2;          if (d1 > PMAX - 1) d1 = PMAX - 1;
                    int d2 = 2 * M_INT - j - p;  if (d2 > PMAX - 1) d2 = PMAX - 1;
                    wv = ACP * (P[d0] - P[d1] - P[d2]);
                }
                W[r][u] = wv;
            }
        }
    }
    __syncthreads();

    const int k = (blockIdx.x * 256 + tid) * 4;

    float4 v0 = load_row_clamped(values, jlo, k);
    float4 v1 = load_row_clamped(values, jlo + 1, k);
    float4 acc[R_PER];
    #pragma unroll
    for (int r = 0; r < R_PER; r++) acc[r] = make_float4(0.f, 0.f, 0.f, 0.f);

    #pragma unroll
    for (int u = 0; u < WIN; u++) {
        float4 v2 = load_row_clamped(values, jlo + u + 2, k);   // unconditional
        float rx = (v2.x - v1.x) - (v1.x - v0.x);
        float ry = (v2.y - v1.y) - (v1.y - v0.y);
        float rz = (v2.z - v1.z) - (v1.z - v0.z);
        float rw = (v2.w - v1.w) - (v1.w - v0.w);
        #pragma unroll
        for (int r = 0; r < R_PER; r++) {
            const float wv = W[r][u];
            acc[r].x = fmaf(wv, rx, acc[r].x);
            acc[r].y = fmaf(wv, ry, acc[r].y);
            acc[r].z = fmaf(wv, rz, acc[r].z);
            acc[r].w = fmaf(wv, rw, acc[r].w);
        }
        v0 = v1; v1 = v2;
    }

    #pragma unroll
    for (int r = 0; r < R_PER; r++)
        *reinterpret_cast<float4*>(g_gamma + (size_t)(g0 + r) * K_FEAT + k) = acc[r];
}

// ---------------------------------------------------------------------------
// Kernel 2: evaluation. Per-j coefficients (a,b,wa,wb) depend only on the
// block's segment s, so precompute them once into smem (first `count` threads)
// and make the inner loop LDS.128-broadcast + 16 FMA + STG.128.
// ---------------------------------------------------------------------------
__global__ void __launch_bounds__(256) spline_eval_kernel(
    const float* __restrict__ values, float* __restrict__ out, int ne1) {

    __shared__ float4 C[40];                                 // <= 33 used

    const int s = blockIdx.y;                                // 0..254
    const int tid = threadIdx.x;
    const int k = (blockIdx.x * blockDim.x + tid) * 4;

    const int jstart = (s * ne1 + 254) / 255;                // ceil(s*ne1/255)
    const int jend   = (s < 254) ? ((s + 1) * ne1 + 254) / 255 - 1 : ne1;
    const int count  = jend - jstart + 1;

    if (tid < count) {
        const float inv_ne1 = 1.0f / (float)ne1;
        const float w = 1.0f / (6.0f * 255.0f * 255.0f);     // h^2/6
        const int j = jstart + tid;
        float b  = (float)(j * 255 - s * ne1) * inv_ne1;     // in [0,1]
        float a  = 1.0f - b;
        float wa = (a * a * a - a) * w;
        float wb = (b * b * b - b) * w;
        C[tid] = make_float4(a, b, wa, wb);
    }

    const float4 y0 = *reinterpret_cast<const float4*>(values  + (size_t)s       * K_FEAT + k);
    const float4 y1 = *reinterpret_cast<const float4*>(values  + (size_t)(s + 1) * K_FEAT + k);
    const float4 q0 = *reinterpret_cast<const float4*>(g_gamma + (size_t)s       * K_FEAT + k);
    const float4 q1 = *reinterpret_cast<const float4*>(g_gamma + (size_t)(s + 1) * K_FEAT + k);

    __syncthreads();

    float* orow = out + (size_t)jstart * K_FEAT + k;
    #pragma unroll 4
    for (int i = 0; i < count; i++) {
        const float4 c = C[i];                               // broadcast LDS.128
        float4 o;
        o.x = fmaf(c.x, y0.x, fmaf(c.y, y1.x, fmaf(c.z, q0.x, c.w * q1.x)));
        o.y = fmaf(c.x, y0.y, fmaf(c.y, y1.y, fmaf(c.z, q0.y, c.w * q1.y)));
        o.z = fmaf(c.x, y0.z, fmaf(c.y, y1.z, fmaf(c.z, q0.z, c.w * q1.z)));
        o.w = fmaf(c.x, y0.w, fmaf(c.y, y1.w, fmaf(c.z, q0.w, c.w * q1.w)));
        __stcs(reinterpret_cast<float4*>(orow), o);
        orow += K_FEAT;
    }
}

extern "C" void kernel_launch(void* const* d_in, const int* in_sizes, int n_in,
                              void* d_out, int out_size) {
    const float* values = (const float*)d_in[0];
    float* out = (float*)d_out;

    const int n_eval = out_size / K_FEAT;
    const int ne1 = n_eval - 1;

    dim3 ggrid(K_FEAT / (256 * 4), N_CTRL / R_PER);          // (4, 128)
    spline_gamma_kernel<<<ggrid, 256>>>(values);

    dim3 egrid(K_FEAT / (256 * 4), N_CTRL - 1);              // (4, 255)
    spline_eval_kernel<<<egrid, 256>>>(values, out, ne1);
}

// round 13
// speedup vs baseline: 1.2199x; 1.0759x over previous
#include <cuda_runtime.h>
#include <cuda_bf16.h>

#define K_FEAT 4096
#define N_CTRL 256
#define M_INT  254       // interior knots
#define HALF   6         // conv half-width; truncation ~rho^7 -> ~1e-7 contribution
#define WIN    (2 + 2 * HALF)   // 14 taps: union window for gamma rows s, s+1
#define PMAX   64        // signed-power table (zeros beyond 48)

__device__ __forceinline__ float4 load_row_clamped(const float* __restrict__ values,
                                                   int row, int k) {
    int r = row < 0 ? 0 : (row > N_CTRL - 1 ? N_CTRL - 1 : row);
    return *reinterpret_cast<const float4*>(values + (size_t)r * K_FEAT + k);
}

// ---------------------------------------------------------------------------
// Single fused kernel. gamma rows come from the closed-form inverse of the
// uniform [1 4 1] system: (M^-1)_{pj} = A*rho^|p-j| - A*rho^(p+j+2)
// - A*rho^(2m-p-j), rho=-(2-sqrt(3)), A=1/(2*sqrt(3)). Each block (segment s,
// 1024-col strip) computes ONLY gamma[s], gamma[s+1] via a 14-tap register
// convolution (112 FMA, 16 unconditional clamped loads — cheap enough to hide
// under the write stream), then streams its ~32 output rows. One launch: no
// gamma kernel, no scratch, no inter-kernel gap. (R5's fused failure used a
// 4x heavier prologue at half the block count; this fixes both.)
// ---------------------------------------------------------------------------
__global__ void __launch_bounds__(256) spline_fused_kernel(
    const float* __restrict__ values, float* __restrict__ out, int ne1) {

    __shared__ float P[PMAX];
    __shared__ float W[2][WIN];

    const int tid = threadIdx.x;
    const int s   = blockIdx.y;               // segment, 0..254
    const int jlo = s - 1 - HALF;             // tap index of slot u=0

    if (tid == 0) {
        const float rho = -0.26794919243112270647f;   // -(2-sqrt(3))
        const float ACP = 0.28867513459481288225f * 6.0f * 255.0f * 255.0f; // A*6/h^2
        float pw = 1.0f;
        for (int d = 0; d < 48; d++) { P[d] = pw; pw *= rho; }
        for (int d = 48; d < PMAX; d++) P[d] = 0.0f;
        for (int r = 0; r < 2; r++) {
            const int g = s + r;              // gamma row (0..255)
            const int p = g - 1;              // interior index
            for (int u = 0; u < WIN; u++) {
                const int j = jlo + u;
                float wv = 0.0f;
                if (g >= 1 && g <= M_INT && j >= 0 && j < M_INT && abs(j - p) <= HALF) {
                    int d0 = abs(j - p);
                    int d1 = j + p + 2;          if (d1 > PMAX - 1) d1 = PMAX - 1;
                    int d2 = 2 * M_INT - j - p;  if (d2 > PMAX - 1) d2 = PMAX - 1;
                    wv = ACP * (P[d0] - P[d1] - P[d2]);
                }
                W[r][u] = wv;
            }
        }
    }
    __syncthreads();

    const int k = (blockIdx.x * 256 + tid) * 4;

    // --- gamma[s], gamma[s+1] via 14-tap convolution (rolling 3-row window) ---
    float4 v0 = load_row_clamped(values, jlo, k);
    float4 v1 = load_row_clamped(values, jlo + 1, k);
    float4 q0 = make_float4(0.f, 0.f, 0.f, 0.f);
    float4 q1 = make_float4(0.f, 0.f, 0.f, 0.f);

    #pragma unroll
    for (int u = 0; u < WIN; u++) {
        float4 v2 = load_row_clamped(values, jlo + u + 2, k);   // unconditional
        float rx = (v2.x - v1.x) - (v1.x - v0.x);
        float ry = (v2.y - v1.y) - (v1.y - v0.y);
        float rz = (v2.z - v1.z) - (v1.z - v0.z);
        float rw = (v2.w - v1.w) - (v1.w - v0.w);
        float w0 = W[0][u], w1 = W[1][u];
        q0.x = fmaf(w0, rx, q0.x); q0.y = fmaf(w0, ry, q0.y);
        q0.z = fmaf(w0, rz, q0.z); q0.w = fmaf(w0, rw, q0.w);
        q1.x = fmaf(w1, rx, q1.x); q1.y = fmaf(w1, ry, q1.y);
        q1.z = fmaf(w1, rz, q1.z); q1.w = fmaf(w1, rw, q1.w);
        v0 = v1; v1 = v2;
    }

    // --- evaluate & stream this segment's rows (proven R6 eval body) ---
    const float4 y0 = load_row_clamped(values, s, k);
    const float4 y1 = load_row_clamped(values, s + 1, k);

    const int jstart = (s * ne1 + 254) / 255;                // ceil(s*ne1/255)
    const int jend   = (s < 254) ? ((s + 1) * ne1 + 254) / 255 - 1 : ne1;

    const float inv_ne1 = 1.0f / (float)ne1;
    const float w = 1.0f / (6.0f * 255.0f * 255.0f);         // h^2/6
    const int base = s * ne1;

    #pragma unroll 4
    for (int j = jstart; j <= jend; j++) {
        float b  = (float)(j * 255 - base) * inv_ne1;        // in [0,1]
        float a  = 1.0f - b;
        float wa = (a * a * a - a) * w;
        float wb = (b * b * b - b) * w;
        float4 o;
        o.x = fmaf(a, y0.x, fmaf(b, y1.x, fmaf(wa, q0.x, wb * q1.x)));
        o.y = fmaf(a, y0.y, fmaf(b, y1.y, fmaf(wa, q0.y, wb * q1.y)));
        o.z = fmaf(a, y0.z, fmaf(b, y1.z, fmaf(wa, q0.z, wb * q1.z)));
        o.w = fmaf(a, y0.w, fmaf(b, y1.w, fmaf(wa, q0.w, wb * q1.w)));
        __stcs(reinterpret_cast<float4*>(out + (size_t)j * K_FEAT + k), o);
    }
}

extern "C" void kernel_launch(void* const* d_in, const int* in_sizes, int n_in,
                              void* d_out, int out_size) {
    const float* values = (const float*)d_in[0];
    float* out = (float*)d_out;

    const int n_eval = out_size / K_FEAT;
    const int ne1 = n_eval - 1;

    dim3 grid(K_FEAT / (256 * 4), N_CTRL - 1);               // (4, 255)
    spline_fused_kernel<<<grid, 256>>>(values, out, ne1);
}